// round 6
// baseline (speedup 1.0000x reference)
#include <cuda_runtime.h>
#include <stdint.h>

// Morton encode: out[b,c, morton(i,j)] = x[b,c,i,j], N=256.
// morton bits: bit0=j0, bit1=i0, bit2=j1, bit3=i1, ...
// Gather form: out[m] = x[i(m), j(m)], j = even bits of m, i = odd bits.
//
// Each thread handles 16 consecutive outputs m..m+15 (m % 16 == 0):
// i%4==0, j%4==0; outputs are the 4x4 block rows i..i+3 x cols j..j+3 in
// Morton order -> 4 aligned float4 loads (row stride 64 float4), register
// shuffle, 4 contiguous float4 stores. MLP=4 independent loads/thread.
// Streaming hints: input read once (__ldcs), output written once (__stcs).

static __global__ void __launch_bounds__(256)
morton_gather_16(const float4* __restrict__ in, float4* __restrict__ out,
                 unsigned ngroups) {
    unsigned stride = gridDim.x * blockDim.x;
    for (unsigned g = blockIdx.x * blockDim.x + threadIdx.x; g < ngroups;
         g += stride) {
        unsigned plane = g >> 12;             // 4096 groups of 16 per plane
        unsigned m = (g & 4095u) << 4;        // output element index in plane

        // Deinterleave: j = even bits, i = odd bits (8 bits each).
        unsigned j = m & 0x5555u;
        j = (j | (j >> 1)) & 0x3333u;
        j = (j | (j >> 2)) & 0x0F0Fu;
        j = (j | (j >> 4)) & 0x00FFu;         // multiple of 4

        unsigned i = (m >> 1) & 0x5555u;
        i = (i | (i >> 1)) & 0x3333u;
        i = (i | (i >> 2)) & 0x0F0Fu;
        i = (i | (i >> 4)) & 0x00FFu;         // multiple of 4

        // float4 index of x[i, j] within the full tensor
        unsigned src = (plane << 14) + (i << 6) + (j >> 2);
        float4 r0 = __ldcs(&in[src]);          // row i
        float4 r1 = __ldcs(&in[src + 64]);     // row i+1
        float4 r2 = __ldcs(&in[src + 128]);    // row i+2
        float4 r3 = __ldcs(&in[src + 192]);    // row i+3

        float4 o0 = make_float4(r0.x, r0.y, r1.x, r1.y);
        float4 o1 = make_float4(r0.z, r0.w, r1.z, r1.w);
        float4 o2 = make_float4(r2.x, r2.y, r3.x, r3.y);
        float4 o3 = make_float4(r2.z, r2.w, r3.z, r3.w);

        unsigned dst = g << 2;                 // four float4 per group
        __stcs(&out[dst],     o0);
        __stcs(&out[dst + 1], o1);
        __stcs(&out[dst + 2], o2);
        __stcs(&out[dst + 3], o3);
    }
}

extern "C" void kernel_launch(void* const* d_in, const int* in_sizes, int n_in,
                              void* d_out, int out_size) {
    const float4* in = (const float4*)d_in[0];
    float4* out = (float4*)d_out;

    unsigned ngroups = (unsigned)(out_size >> 4);  // 524,288 for bench shape
    const int threads = 256;
    unsigned blocks = (ngroups + threads - 1) / threads;

    morton_gather_16<<<blocks, threads>>>(in, out, ngroups);
}